// round 3
// baseline (speedup 1.0000x reference)
#include <cuda_runtime.h>
#include <math.h>

#define NB 16
#define NT 128
#define NC 64
#define NU 128
#define UNF 6
#define EPSV 1e-8f
#define TCHUNK 16

#define RANKS 4               // CTAs per cluster (per batch element)
#define JPC (NU / RANKS)      // 32 post-units per CTA
#define TPJ (128 / JPC)       // 4 threads per post-unit
#define PRE (NU / TPJ)        // 32 pre-units per thread

// Scratch (allocation-free rule: __device__ globals)
__device__ float g_sensN[NB * NT * NU];
__device__ float g_sensD[NB * NT * NU];
__device__ float g_SA[NC * NU];
__device__ float g_SB[NC * NU];
__device__ float g_SW[NC * NU];

__device__ __forceinline__ float tanha(float x) {
    float r;
    asm("tanh.approx.f32 %0, %1;" : "=f"(r) : "f"(x));
    return r;
}

__device__ __forceinline__ float softplusf(float x) {
    return log1pf(__expf(x));
}

__device__ __forceinline__ unsigned smem_u32(const void* p) {
    unsigned a;
    asm("{ .reg .u64 t; cvta.to.shared.u64 t, %1; cvt.u32.u64 %0, t; }"
        : "=r"(a) : "l"(p));
    return a;
}

// ---------------------------------------------------------------------------
// Kernel 0: transform sensory params once (fp32)
// ---------------------------------------------------------------------------
__global__ void k_sens_prep(const float* __restrict__ ss,
                            const float* __restrict__ smu,
                            const float* __restrict__ sw,
                            const float* __restrict__ serev) {
    int idx = blockIdx.x * blockDim.x + threadIdx.x;
    if (idx < NC * NU) {
        float a = 0.5f * ss[idx];
        g_SA[idx] = a;
        g_SB[idx] = -a * smu[idx];
        g_SW[idx] = softplusf(sw[idx]) * serev[idx];
    }
}

// ---------------------------------------------------------------------------
// Kernel 1: sensory pre-pass (fp32, fully parallel over b,t)
// ---------------------------------------------------------------------------
__global__ void __launch_bounds__(128) k_sensory(const float* __restrict__ x,
                                                 const float* __restrict__ iw,
                                                 const float* __restrict__ ib) {
    extern __shared__ float sm[];
    float* sSA = sm;
    float* sSB = sm + NC * NU;
    float* sSW = sm + 2 * NC * NU;
    float* xb  = sm + 3 * NC * NU;  // TCHUNK*NC

    int b  = blockIdx.x / (NT / TCHUNK);
    int t0 = (blockIdx.x % (NT / TCHUNK)) * TCHUNK;
    int tid = threadIdx.x;

    for (int idx = tid; idx < NC * NU; idx += 128) {
        sSA[idx] = g_SA[idx];
        sSB[idx] = g_SB[idx];
        sSW[idx] = g_SW[idx];
    }
    for (int idx = tid; idx < TCHUNK * NC; idx += 128) {
        int tt = idx / NC, i = idx % NC;
        xb[idx] = fmaf(x[(b * NT + t0 + tt) * NC + i], iw[i], ib[i]);
    }
    __syncthreads();

    int j = tid;
    for (int tt = 0; tt < TCHUNK; tt++) {
        float wn = 0.f, wd = 0.f;
#pragma unroll 8
        for (int i = 0; i < NC; i++) {
            float xv = xb[tt * NC + i];
            float y  = fmaf(sSA[i * NU + j], xv, sSB[i * NU + j]);
            float s  = fmaf(0.5f, tanha(y), 0.5f);
            float we = sSW[i * NU + j];
            wn = fmaf(we, s, wn);
            wd = fmaf(fabsf(we), s, wd);
        }
        int o = (b * NT + t0 + tt) * NU + j;
        g_sensN[o] = wn;
        g_sensD[o] = wd;
    }
}

// ---------------------------------------------------------------------------
// Kernel 2: main recurrence, cluster-parallel.
// Cluster of RANKS=4 CTAs per batch element. CTA `rank` owns post-units
// [rank*32, rank*32+32). Thread t: jloc = t/4, qtr = t%4; handles post-unit
// j = rank*32 + jloc over pre-units [qtr*32, qtr*32+32). All params fp32 in
// registers. Partial (q, r) reduced over the 4-lane group via shfl.bfly.
// v state (128 fp32) replicated per-CTA in smem, double-buffered; new v's
// broadcast to all cluster CTAs via mapa + st.shared::cluster, synchronized
// with one barrier.cluster per unfold (release/acquire covers DSMEM stores).
// ---------------------------------------------------------------------------
__global__ void __launch_bounds__(128, 1) __cluster_dims__(RANKS, 1, 1)
k_main(const float* __restrict__ h0,
       const float* __restrict__ gleak,
       const float* __restrict__ vleak,
       const float* __restrict__ cm,
       const float* __restrict__ sigma,
       const float* __restrict__ mu,
       const float* __restrict__ w,
       const float* __restrict__ erev,
       const float* __restrict__ ow,
       const float* __restrict__ ob,
       float* __restrict__ out,
       int write_hfinal) {
    __shared__ float vsm[2 * NU];

    int rank = blockIdx.x;
    int b    = blockIdx.y;
    int t    = threadIdx.x;
    int jloc = t / TPJ;
    int qtr  = t % TPJ;
    int j    = rank * JPC + jloc;

    // ---- Prologue: this thread's 32 pre-unit params into registers ----
    float pa[PRE], pb[PRE], pw[PRE], pq[PRE];
    float swe = 0.f, swa = 0.f;
#pragma unroll
    for (int k = 0; k < PRE; k++) {
        int i   = qtr * PRE + k;
        int idx = i * NU + j;
        float sg = sigma[idx];
        pa[k] = 0.5f * sg;
        pb[k] = -pa[k] * mu[idx];
        float ww = softplusf(w[idx]) * erev[idx];
        pw[k] = ww;
        pq[k] = fabsf(ww);
        swe += ww;
        swa += pq[k];
    }
    // reduce column sums over the 4-lane group
    swe += __shfl_xor_sync(0xFFFFFFFFu, swe, 1);
    swe += __shfl_xor_sync(0xFFFFFFFFu, swe, 2);
    swa += __shfl_xor_sync(0xFFFFFFFFu, swa, 1);
    swa += __shfl_xor_sync(0xFFFFFFFFu, swa, 2);

    float gl  = softplusf(gleak[j]);
    float cmt = softplusf(cm[j]) * (float)UNF;
    float K1  = fmaf(gl, vleak[j], 0.5f * swe);
    float K2  = cmt + gl + 0.5f * swa + EPSV;
    float owj = ow[j], obj = ob[j];

    // init v buffer 0 with h0 (full 128 units, local copy per CTA)
    vsm[t] = h0[b * NU + t];
    __syncthreads();
    float vloc = vsm[j];

    // peer smem base addresses for the v buffer (all 4 ranks, incl. self)
    unsigned vbase = smem_u32(vsm);
    unsigned peer[RANKS];
#pragma unroll
    for (int r = 0; r < RANKS; r++) {
        asm("mapa.shared::cluster.u32 %0, %1, %2;"
            : "=r"(peer[r]) : "r"(vbase), "r"(r));
    }

    int p = 0;
#pragma unroll 1
    for (int ts = 0; ts < NT; ts++) {
        int so = (b * NT + ts) * NU + j;
        float base_n = K1 + g_sensN[so];
        float base_d = K2 + g_sensD[so];
#pragma unroll 1
        for (int u = 0; u < UNF; u++) {
            const float4* v4 = (const float4*)(vsm + p * NU + qtr * PRE);
            float q = 0.f, r = 0.f;
#pragma unroll
            for (int c = 0; c < PRE / 4; c++) {
                float4 vv = v4[c];
                float t0 = tanha(fmaf(pa[4 * c + 0], vv.x, pb[4 * c + 0]));
                float t1 = tanha(fmaf(pa[4 * c + 1], vv.y, pb[4 * c + 1]));
                float t2 = tanha(fmaf(pa[4 * c + 2], vv.z, pb[4 * c + 2]));
                float t3 = tanha(fmaf(pa[4 * c + 3], vv.w, pb[4 * c + 3]));
                q = fmaf(pw[4 * c + 0], t0, q);
                r = fmaf(pq[4 * c + 0], t0, r);
                q = fmaf(pw[4 * c + 1], t1, q);
                r = fmaf(pq[4 * c + 1], t1, r);
                q = fmaf(pw[4 * c + 2], t2, q);
                r = fmaf(pq[4 * c + 2], t2, r);
                q = fmaf(pw[4 * c + 3], t3, q);
                r = fmaf(pq[4 * c + 3], t3, r);
            }
            q += __shfl_xor_sync(0xFFFFFFFFu, q, 1);
            q += __shfl_xor_sync(0xFFFFFFFFu, q, 2);
            r += __shfl_xor_sync(0xFFFFFFFFu, r, 1);
            r += __shfl_xor_sync(0xFFFFFFFFu, r, 2);

            float num = fmaf(cmt, vloc, base_n) + 0.5f * q;
            float den = base_d + 0.5f * r;
            vloc = __fdividef(num, den);

            // broadcast my post-unit's new v to every CTA in the cluster
            if (qtr == 0) {
                unsigned off = (unsigned)(((p ^ 1) * NU + j) * 4);
#pragma unroll
                for (int rr = 0; rr < RANKS; rr++) {
                    asm volatile("st.shared::cluster.f32 [%0], %1;"
                                 :: "r"(peer[rr] + off), "f"(vloc) : "memory");
                }
            }
            // release my stores / acquire peers' stores
            asm volatile("barrier.cluster.arrive.aligned;" ::: "memory");
            asm volatile("barrier.cluster.wait.aligned;" ::: "memory");
            p ^= 1;
        }
        if (qtr == 0) {
            out[so] = fmaf(vloc, owj, obj);
        }
    }
    if (write_hfinal && qtr == 0) {
        out[NB * NT * NU + b * NU + j] = vloc;
    }
}

// ---------------------------------------------------------------------------
extern "C" void kernel_launch(void* const* d_in, const int* in_sizes, int n_in,
                              void* d_out, int out_size) {
    const float* x      = (const float*)d_in[0];
    const float* h0     = (const float*)d_in[1];
    const float* gleak  = (const float*)d_in[2];
    const float* vleak  = (const float*)d_in[3];
    const float* cm     = (const float*)d_in[4];
    const float* sigma  = (const float*)d_in[5];
    const float* mu     = (const float*)d_in[6];
    const float* w      = (const float*)d_in[7];
    const float* erev   = (const float*)d_in[8];
    const float* ss     = (const float*)d_in[9];
    const float* smu    = (const float*)d_in[10];
    const float* sw     = (const float*)d_in[11];
    const float* serev  = (const float*)d_in[12];
    const float* iw     = (const float*)d_in[13];
    const float* ibias  = (const float*)d_in[14];
    const float* outw   = (const float*)d_in[15];
    const float* outb   = (const float*)d_in[16];

    const int SENS_SMEM = (3 * NC * NU + TCHUNK * NC) * (int)sizeof(float);  // 100 KB
    cudaFuncSetAttribute(k_sensory, cudaFuncAttributeMaxDynamicSharedMemorySize, SENS_SMEM);

    int write_hfinal = (out_size >= NB * NT * NU + NB * NU) ? 1 : 0;

    k_sens_prep<<<(NC * NU + 255) / 256, 256>>>(ss, smu, sw, serev);
    k_sensory<<<NB * (NT / TCHUNK), 128, SENS_SMEM>>>(x, iw, ibias);

    dim3 grid(RANKS, NB);
    k_main<<<grid, 128>>>(h0, gleak, vleak, cm, sigma, mu, w, erev,
                          outw, outb, (float*)d_out, write_hfinal);
}